// round 9
// baseline (speedup 1.0000x reference)
#include <cuda_runtime.h>

#define NUM_USERS 50000
#define NUM_ITEMS 50000
#define D 64
#define DV 16
#define N_NODES (NUM_USERS + NUM_ITEMS)
#define N_EDGES 500000
#define NNZ_G 1000000
#define NNZ_GX 2000000
#define BATCH 8192

// ---- static device scratch (no allocation; all zero-init at load) ----
__device__ float g_A[(size_t)N_NODES * D];
__device__ float g_B[(size_t)N_NODES * D];     // zeroed by k_combine each layer (static zero first call)
__device__ float g_U[(size_t)N_NODES * D];     // ditto
__device__ float g_acc[(size_t)N_NODES * D];   // zeroed by k_init each call
__device__ float g_deg[N_NODES];               // counted in k_scatter, zeroed in k_dot

// CSR of gx nnz grouped by destination EDGE (500k bins, avg 4 entries)
__device__ int  g_ecnt[N_EDGES];               // zeroed by k_scan after use
__device__ int  g_eoff[N_EDGES + 1];
__device__ int  g_ecur[N_EDGES];
__device__ int4 g_eseg[NNZ_GX];                // {su | cidx<<17, si(+50k), vbits, pad}

// fire-and-forget vector reduction (RED.E.ADD.F32x4), sm_90+
__device__ __forceinline__ void red_add_f32x4(float4* addr, float4 v) {
    asm volatile("red.global.add.v4.f32 [%0], {%1, %2, %3, %4};"
                 :: "l"(addr), "f"(v.x), "f"(v.y), "f"(v.z), "f"(v.w)
                 : "memory");
}

// 1: count gx nnz per destination edge (precondition ecnt=0: static init / k_scan cleanup)
__global__ void k_count(const int* __restrict__ gxr) {
    int t = blockIdx.x * blockDim.x + threadIdx.x;
    if (t >= NNZ_GX) return;
    atomicAdd(&g_ecnt[gxr[t]], 1);
}

// 2: single-block exclusive scan of 500k bins; zero ecnt behind itself
__global__ void k_scan() {
    __shared__ int ssum[1024];
    int tid = threadIdx.x;
    const int n = N_EDGES;
    int chunk = (n + 1023) / 1024;
    int beg = tid * chunk;
    int end = beg + chunk; if (end > n) end = n; if (beg > n) beg = n;
    int s = 0;
    for (int i = beg; i < end; ++i) s += g_ecnt[i];
    ssum[tid] = s;
    __syncthreads();
    for (int o = 1; o < 1024; o <<= 1) {
        int v = (tid >= o) ? ssum[tid - o] : 0;
        __syncthreads();
        ssum[tid] += v;
        __syncthreads();
    }
    int run = (tid == 0) ? 0 : ssum[tid - 1];
    for (int i = beg; i < end; ++i) {
        int c = g_ecnt[i];
        g_eoff[i] = run;
        g_ecur[i] = run;
        g_ecnt[i] = 0;          // cleanup for next call
        run += c;
    }
    if (tid == 1023) g_eoff[n] = ssum[1023];
}

// 3: scatter gx entries into edge-sorted array; also count node degrees
//    (precondition deg=0: static init / k_dot cleanup)
__global__ void k_scatter(const int* __restrict__ gxr, const int* __restrict__ gxc,
                          const float* __restrict__ gxv,
                          const int* __restrict__ tu, const int* __restrict__ ti,
                          const int* __restrict__ i2c) {
    int t = blockIdx.x * blockDim.x + threadIdx.x;
    if (t < NNZ_GX) {
        int r = gxr[t];
        int c = gxc[t];
        int su = tu[c];
        int tic = ti[c];
        int cidx = i2c[tic];
        int p = atomicAdd(&g_ecur[r], 1);
        g_eseg[p] = make_int4(su | (cidx << 17), NUM_USERS + tic,
                              __float_as_int(gxv[t]), 0);
    }
    if (t < N_EDGES) {
        atomicAdd(&g_deg[tu[t]], 1.f);
        atomicAdd(&g_deg[NUM_USERS + ti[t]], 1.f);
    }
}

// 4: init embeddings + acc (B,U maintained zero by combine)
__global__ void k_init(const float* __restrict__ ue, const float* __restrict__ ie) {
    int t = blockIdx.x * blockDim.x + threadIdx.x;
    if (t >= N_NODES * DV) return;
    float4 v;
    if (t < NUM_USERS * DV) v = ((const float4*)ue)[t];
    else                    v = ((const float4*)ie)[t - NUM_USERS * DV];
    ((float4*)g_A)[t]   = v;
    ((float4*)g_acc)[t] = make_float4(0.f, 0.f, 0.f, 0.f);
}

// push spmm (R4-proven): B[r] += v * A[c], 2 nnz per thread
__global__ void __launch_bounds__(256) k_spmm_g(const int* __restrict__ rows,
                                                const int* __restrict__ cols,
                                                const float* __restrict__ vals) {
    int t = blockIdx.x * blockDim.x + threadIdx.x;   // < NNZ_G/2 * 16 = 8M
    int p = t >> 4;
    int j = t & 15;
    if (p >= NNZ_G / 2) return;
    int2   r2 = ((const int2*)rows)[p];
    int2   c2 = ((const int2*)cols)[p];
    float2 v2 = ((const float2*)vals)[p];
    const float4* Av = (const float4*)g_A;
    float4 x0 = Av[c2.x * DV + j];
    float4 x1 = Av[c2.y * DV + j];
    float4 y0 = make_float4(v2.x * x0.x, v2.x * x0.y, v2.x * x0.z, v2.x * x0.w);
    float4 y1 = make_float4(v2.y * x1.x, v2.y * x1.y, v2.y * x1.z, v2.y * x1.w);
    red_add_f32x4(((float4*)g_B) + r2.x * DV + j, y0);
    red_add_f32x4(((float4*)g_B) + r2.y * DV + j, y1);
}

// edge-aggregated gx push: per (edge e, chunk j), accumulate the ~4 nnz of
// seg(e) in registers, then ONE RED pair to U[tu[e]] / U[50000+ti[e]].
template <int LAYER0>
__global__ void __launch_bounds__(256) k_gx_edge(const int* __restrict__ tu,
                                                 const int* __restrict__ ti,
                                                 const float* __restrict__ cat) {
    int t = blockIdx.x * blockDim.x + threadIdx.x;   // < N_EDGES * 16 = 8M
    int e = t >> 4;
    int j = t & 15;
    if (e >= N_EDGES) return;
    int i = g_eoff[e], end = g_eoff[e + 1];
    if (i == end) return;
    const float4* Bv = (const float4*)g_B;
    const float4* catv = (const float4*)cat;
    float4 au = make_float4(0.f, 0.f, 0.f, 0.f);
    float4 ai = make_float4(0.f, 0.f, 0.f, 0.f);
    for (; i < end; ++i) {
        int4 E = g_eseg[i];
        float v = __int_as_float(E.z);
        float4 x0 = Bv[(E.x & 0x1FFFF) * DV + j];
        float4 x1 = Bv[E.y * DV + j];
        if (LAYER0) {
            int cidx = (E.x >> 17) & 0x1FF;
            float4 c0 = catv[cidx * 32 + j];
            float4 c1 = catv[cidx * 32 + 16 + j];
            x0.x += c0.x; x0.y += c0.y; x0.z += c0.z; x0.w += c0.w;
            x1.x += c1.x; x1.y += c1.y; x1.z += c1.z; x1.w += c1.w;
        }
        au.x += v * x0.x; au.y += v * x0.y; au.z += v * x0.z; au.w += v * x0.w;
        ai.x += v * x1.x; ai.y += v * x1.y; ai.z += v * x1.z; ai.w += v * x1.w;
    }
    int du = tu[e];
    int di = NUM_USERS + ti[e];
    red_add_f32x4(((float4*)g_U) + du * DV + j, au);
    red_add_f32x4(((float4*)g_U) + di * DV + j, ai);
}

// A = 0.5 * (U/(deg+1e-9) + B);  acc += A;  zero B,U for next layer/call
__global__ void k_combine() {
    int t0 = (blockIdx.x * blockDim.x + threadIdx.x) * 2;
    if (t0 >= N_NODES * DV) return;
    float4 z = make_float4(0.f, 0.f, 0.f, 0.f);
    #pragma unroll
    for (int q = 0; q < 2; ++q) {
        int t = t0 + q;
        int n = t >> 4;
        float inv = 0.5f / (g_deg[n] + 1e-9f);
        float4 u = ((const float4*)g_U)[t];
        float4 b = ((const float4*)g_B)[t];
        float4 a;
        a.x = u.x * inv + 0.5f * b.x;
        a.y = u.y * inv + 0.5f * b.y;
        a.z = u.z * inv + 0.5f * b.z;
        a.w = u.w * inv + 0.5f * b.w;
        ((float4*)g_A)[t] = a;
        float4 ac = ((float4*)g_acc)[t];
        ac.x += a.x; ac.y += a.y; ac.z += a.z; ac.w += a.w;
        ((float4*)g_acc)[t] = ac;
        ((float4*)g_B)[t] = z;
        ((float4*)g_U)[t] = z;
    }
}

// gamma[b] = dot(acc[u], acc[50000+i]) / 9; also zero deg for next call
__global__ void k_dot(const int* __restrict__ users, const int* __restrict__ items,
                      float* __restrict__ out) {
    int t = blockIdx.x * blockDim.x + threadIdx.x;
    if (t < N_NODES) g_deg[t] = 0.f;            // cleanup for next call
    int b = t >> 5;
    if (b >= BATCH) return;
    int lane = t & 31;
    const float2* au = (const float2*)(g_acc + (size_t)users[b] * D);
    const float2* ai = (const float2*)(g_acc + (size_t)(NUM_USERS + items[b]) * D);
    float2 x = au[lane], y = ai[lane];
    float s = x.x * y.x + x.y * y.y;
    #pragma unroll
    for (int o = 16; o; o >>= 1) s += __shfl_down_sync(0xffffffffu, s, o);
    if (lane == 0) out[b] = s * (1.f / 9.f);
}

extern "C" void kernel_launch(void* const* d_in, const int* in_sizes, int n_in,
                              void* d_out, int out_size) {
    const float* user_emb = (const float*)d_in[0];
    const float* item_emb = (const float*)d_in[1];
    const float* cat_emb  = (const float*)d_in[2];
    const float* g_vals   = (const float*)d_in[3];
    const float* gx_vals  = (const float*)d_in[4];
    const int*   g_rows   = (const int*)d_in[5];
    const int*   g_cols   = (const int*)d_in[6];
    const int*   gx_rows  = (const int*)d_in[7];
    const int*   gx_cols  = (const int*)d_in[8];
    const int*   tu       = (const int*)d_in[9];
    const int*   ti       = (const int*)d_in[10];
    const int*   i2c      = (const int*)d_in[11];
    const int*   users    = (const int*)d_in[12];
    const int*   items    = (const int*)d_in[13];
    float* out = (float*)d_out;

    const int TB = 256;
    int node_grid = (N_NODES * DV + TB - 1) / TB;        // 6250
    int comb_grid = (N_NODES * DV / 2 + TB - 1) / TB;    // 3125
    int nnz_grid  = (NNZ_GX + TB - 1) / TB;              // 7813
    int g_grid    = (NNZ_G / 2 * 16) / TB;               // 31250
    int gx_grid   = (N_EDGES * 16) / TB;                 // 31250
    int dot_grid  = (BATCH * 32 + TB - 1) / TB;          // 1024

    k_count<<<nnz_grid, TB>>>(gx_rows);                              // 1
    k_scan<<<1, 1024>>>();                                           // 2
    k_scatter<<<nnz_grid, TB>>>(gx_rows, gx_cols, gx_vals,
                                tu, ti, i2c);                        // 3
    k_init<<<node_grid, TB>>>(user_emb, item_emb);                   // 4
    for (int L = 0; L < 3; ++L) {
        k_spmm_g<<<g_grid, TB>>>(g_rows, g_cols, g_vals);            // 5, 8, 11
        if (L == 0) k_gx_edge<1><<<gx_grid, TB>>>(tu, ti, cat_emb);  // 6, 9, 12
        else        k_gx_edge<0><<<gx_grid, TB>>>(tu, ti, cat_emb);
        k_combine<<<comb_grid, TB>>>();                              // 7, 10, 13
    }
    k_dot<<<dot_grid, TB>>>(users, items, out);                      // 14
}